// round 5
// baseline (speedup 1.0000x reference)
#include <cuda_runtime.h>
#include <cstdint>

// ---------------------------------------------------------------------------
// GRU cell fused kernel for base sm_100 target (NO 'a' suffix available in
// this harness toolchain -> no tcgen05). Uses classic mma.sync tf32 (sm_80+).
//
// gi = x@Wih^T + b_ih ; gh = h@Whh^T + b_hh
// r = sig(gi_r+gh_r); z = sig(gi_z+gh_z); n = tanh(gi_n + r*gh_n)
// h' = (1-z)*n + z*h
//
// CTA tile: M=128 batch rows x N=64 gate cols. 8 warps (4 in M, 2 in N),
// warp tile 32x32 per accumulator set. 4 register accumulator sets:
// r,z (accumulate both phases), gi_n (phase 0), gh_n (phase 1).
// Inputs pre-rounded to tf32 (cvt.rna) to avoid mma truncation bias.
// ---------------------------------------------------------------------------

#define HID   1024
#define BATCH 16384
#define TM    128
#define TN    64
#define KC    32
#define LDSW  36                      // padded smem row stride in floats
#define A_FLOATS   (TM * LDSW)        // 4608
#define STAGE_FLOATS ((TM + 3 * TN) * LDSW)   // 320*36 = 11520
#define STAGE_BYTES  (STAGE_FLOATS * 4)       // 46080
#define NSTG  3
#define SMEM_TOTAL (NSTG * STAGE_BYTES)       // 138240
#define TOT_STAGES 64                 // 2 phases * (1024/32)

// tf32-rounded operand scratch (device globals: allowed scratch mechanism)
__device__ float g_x  [(size_t)BATCH * HID];
__device__ float g_h  [(size_t)BATCH * HID];
__device__ float g_wih[(size_t)3 * HID * HID];
__device__ float g_whh[(size_t)3 * HID * HID];

static __device__ __forceinline__ uint32_t smem_u32(const void* p) {
    uint32_t a;
    asm("{ .reg .u64 t; cvta.to.shared.u64 t, %1; cvt.u32.u64 %0, t; }" : "=r"(a) : "l"(p));
    return a;
}

static __device__ __forceinline__ void cp16(uint32_t saddr, const void* g) {
    asm volatile("cp.async.cg.shared.global [%0], [%1], 16;" :: "r"(saddr), "l"(g));
}

#define CP_COMMIT()  asm volatile("cp.async.commit_group;" ::: "memory")
#define CP_WAIT(N)   asm volatile("cp.async.wait_group %0;" :: "n"(N) : "memory")

#define MMA(C, A, B0, B1)                                                     \
    asm volatile(                                                             \
        "mma.sync.aligned.m16n8k8.row.col.f32.tf32.tf32.f32 "                 \
        "{%0,%1,%2,%3},{%4,%5,%6,%7},{%8,%9},{%0,%1,%2,%3};"                  \
        : "+f"((C)[0]), "+f"((C)[1]), "+f"((C)[2]), "+f"((C)[3])              \
        : "r"((A)[0]), "r"((A)[1]), "r"((A)[2]), "r"((A)[3]),                 \
          "r"(B0), "r"(B1))

// ---------------------------------------------------------------------------
// pre-round fp32 -> tf32 (round-to-nearest) so mma.sync's truncation of the
// low mantissa bits is exact (no systematic bias).
// ---------------------------------------------------------------------------
__global__ void round_tf32_k(const float4* __restrict__ in, float4* __restrict__ out, int n4)
{
    int i = blockIdx.x * blockDim.x + threadIdx.x;
    int stride = gridDim.x * blockDim.x;
    for (; i < n4; i += stride) {
        float4 v = in[i];
        uint32_t a, b, c, d;
        asm("cvt.rna.tf32.f32 %0, %1;" : "=r"(a) : "f"(v.x));
        asm("cvt.rna.tf32.f32 %0, %1;" : "=r"(b) : "f"(v.y));
        asm("cvt.rna.tf32.f32 %0, %1;" : "=r"(c) : "f"(v.z));
        asm("cvt.rna.tf32.f32 %0, %1;" : "=r"(d) : "f"(v.w));
        float4 o;
        o.x = __uint_as_float(a); o.y = __uint_as_float(b);
        o.z = __uint_as_float(c); o.w = __uint_as_float(d);
        out[i] = o;
    }
}

// one stage of MMAs on a filled buffer. aN is gi_n (phase 0) or gh_n (phase 1).
static __device__ __forceinline__ void stage_compute(
    const float* __restrict__ As, const float* __restrict__ Bs,
    int wm, int wn, int r4, int c4,
    float (&aR)[2][4][4], float (&aZ)[2][4][4], float (&aN)[2][4][4])
{
    #pragma unroll
    for (int ks = 0; ks < 4; ++ks) {
        uint32_t a[2][4];
        #pragma unroll
        for (int mb = 0; mb < 2; ++mb) {
            const float* ap = As + (wm * 32 + mb * 16 + r4) * LDSW + ks * 8 + c4;
            a[mb][0] = __float_as_uint(ap[0]);
            a[mb][1] = __float_as_uint(ap[8 * LDSW]);
            a[mb][2] = __float_as_uint(ap[4]);
            a[mb][3] = __float_as_uint(ap[8 * LDSW + 4]);
        }
        #pragma unroll
        for (int nb = 0; nb < 4; ++nb) {
            const float* bp = Bs + (wn * 32 + nb * 8 + r4) * LDSW + ks * 8 + c4;
            {   // gate 0 -> r
                uint32_t b0 = __float_as_uint(bp[0]), b1 = __float_as_uint(bp[4]);
                MMA(aR[0][nb], a[0], b0, b1);
                MMA(aR[1][nb], a[1], b0, b1);
            }
            {   // gate 1 -> z
                const float* bq = bp + 64 * LDSW;
                uint32_t b0 = __float_as_uint(bq[0]), b1 = __float_as_uint(bq[4]);
                MMA(aZ[0][nb], a[0], b0, b1);
                MMA(aZ[1][nb], a[1], b0, b1);
            }
            {   // gate 2 -> gi_n / gh_n
                const float* bq = bp + 128 * LDSW;
                uint32_t b0 = __float_as_uint(bq[0]), b1 = __float_as_uint(bq[4]);
                MMA(aN[0][nb], a[0], b0, b1);
                MMA(aN[1][nb], a[1], b0, b1);
            }
        }
    }
}

__global__ void __launch_bounds__(256, 1)
gru_mma_kernel(const float* __restrict__ hprev_f32,
               const float* __restrict__ bih, const float* __restrict__ bhh,
               float* __restrict__ out)
{
    extern __shared__ __align__(128) float smemf[];
    const uint32_t sbase = smem_u32(smemf);
    const int tid = threadIdx.x;
    const int wid = tid >> 5, lane = tid & 31;
    const int wm = wid >> 1, wn = wid & 1;
    const int r4 = lane >> 2, c4 = lane & 3;
    const int j0 = blockIdx.x * TN;    // gate-col tile base within H
    const int m0 = blockIdx.y * TM;    // batch-row tile base

    float aR[2][4][4], aZ[2][4][4], aGI[2][4][4], aGH[2][4][4];
    #pragma unroll
    for (int i = 0; i < 2; ++i)
        #pragma unroll
        for (int j = 0; j < 4; ++j)
            #pragma unroll
            for (int k = 0; k < 4; ++k)
                aR[i][j][k] = aZ[i][j][k] = aGI[i][j][k] = aGH[i][j][k] = 0.f;

    // stage s: phase = s>>5 (0: x/Wih, 1: h/Whh), K offset = (s&31)*32
    auto fill = [&](int s) {
        const int ph = s >> 5;
        const int kk = (s & 31) * KC;
        const float* A = ph ? g_h : g_x;
        const float* W = ph ? g_whh : g_wih;
        const uint32_t sb = sbase + (uint32_t)(s % NSTG) * STAGE_BYTES;
        #pragma unroll
        for (int i = 0; i < 4; ++i) {           // A: 128 rows x 8 chunks
            int idx = tid + (i << 8);
            int row = idx >> 3, ch = idx & 7;
            cp16(sb + (uint32_t)(row * LDSW * 4 + ch * 16),
                 A + (size_t)(m0 + row) * HID + kk + ch * 4);
        }
        const uint32_t bb = sb + A_FLOATS * 4;
        #pragma unroll
        for (int i = 0; i < 6; ++i) {           // B: 192 rows x 8 chunks
            int idx = tid + (i << 8);
            int row = idx >> 3, ch = idx & 7;   // row 0..191
            int gate = row >> 6, n = row & 63;
            cp16(bb + (uint32_t)(row * LDSW * 4 + ch * 16),
                 W + (size_t)(gate * HID + j0 + n) * HID + kk + ch * 4);
        }
    };

    fill(0); CP_COMMIT();
    fill(1); CP_COMMIT();

    for (int s = 0; s < TOT_STAGES; ++s) {
        if (s == TOT_STAGES - 1) { CP_WAIT(0); } else { CP_WAIT(1); }
        __syncthreads();
        if (s + 2 < TOT_STAGES) { fill(s + 2); CP_COMMIT(); }

        const float* As = smemf + (s % NSTG) * STAGE_FLOATS;
        const float* Bs = As + A_FLOATS;
        if (s < 32) stage_compute(As, Bs, wm, wn, r4, c4, aR, aZ, aGI);
        else        stage_compute(As, Bs, wm, wn, r4, c4, aR, aZ, aGH);
    }

    // ---- epilogue: gates + blend, straight from registers ----
    #pragma unroll
    for (int nb = 0; nb < 4; ++nb) {
        const int col = j0 + wn * 32 + nb * 8 + c4 * 2;   // even -> 8B aligned
        const float br0 = bih[col]           + bhh[col];
        const float br1 = bih[col + 1]       + bhh[col + 1];
        const float bz0 = bih[HID + col]     + bhh[HID + col];
        const float bz1 = bih[HID + col + 1] + bhh[HID + col + 1];
        const float2 bgi = *(const float2*)&bih[2 * HID + col];
        const float2 bgh = *(const float2*)&bhh[2 * HID + col];
        #pragma unroll
        for (int mb = 0; mb < 2; ++mb) {
            #pragma unroll
            for (int half = 0; half < 2; ++half) {
                const int row = m0 + wm * 32 + mb * 16 + r4 + half * 8;
                const float2 hp = *(const float2*)&hprev_f32[(size_t)row * HID + col];
                float o[2];
                #pragma unroll
                for (int e = 0; e < 2; ++e) {
                    const int ci = half * 2 + e;
                    float vr = aR [mb][nb][ci] + (e ? br1 : br0);
                    float vz = aZ [mb][nb][ci] + (e ? bz1 : bz0);
                    float gi = aGI[mb][nb][ci] + (e ? bgi.y : bgi.x);
                    float gh = aGH[mb][nb][ci] + (e ? bgh.y : bgh.x);
                    float r = 1.f / (1.f + __expf(-vr));
                    float z = 1.f / (1.f + __expf(-vz));
                    float n = tanhf(fmaf(r, gh, gi));
                    float hpe = e ? hp.y : hp.x;
                    o[e] = fmaf(z, hpe - n, n);
                }
                *(float2*)&out[(size_t)row * HID + col] = make_float2(o[0], o[1]);
            }
        }
    }
}

extern "C" void kernel_launch(void* const* d_in, const int* in_sizes, int n_in,
                              void* d_out, int out_size)
{
    (void)in_sizes; (void)n_in; (void)out_size;
    const float* x   = (const float*)d_in[0];
    const float* h   = (const float*)d_in[1];
    const float* wih = (const float*)d_in[2];
    const float* whh = (const float*)d_in[3];
    const float* bih = (const float*)d_in[4];
    const float* bhh = (const float*)d_in[5];
    float* out = (float*)d_out;

    void *px, *ph, *pwih, *pwhh;
    cudaGetSymbolAddress(&px,   g_x);
    cudaGetSymbolAddress(&ph,   g_h);
    cudaGetSymbolAddress(&pwih, g_wih);
    cudaGetSymbolAddress(&pwhh, g_whh);

    const int NXH = BATCH * HID / 4;       // 4194304 float4
    const int NW  = 3 * HID * HID / 4;     // 786432 float4
    round_tf32_k<<<4096, 256>>>((const float4*)x,   (float4*)px,   NXH);
    round_tf32_k<<<4096, 256>>>((const float4*)h,   (float4*)ph,   NXH);
    round_tf32_k<<<3072, 256>>>((const float4*)wih, (float4*)pwih, NW);
    round_tf32_k<<<3072, 256>>>((const float4*)whh, (float4*)pwhh, NW);

    static int smem_set = 0;
    if (!smem_set) {
        cudaFuncSetAttribute(gru_mma_kernel,
                             cudaFuncAttributeMaxDynamicSharedMemorySize, SMEM_TOTAL);
        smem_set = 1;
    }
    dim3 grid(HID / TN, BATCH / TM);   // (16, 128)
    gru_mma_kernel<<<grid, 256, SMEM_TOTAL>>>(h, bih, bhh, out);
}